// round 11
// baseline (speedup 1.0000x reference)
#include <cuda_runtime.h>
#include <cstdint>
#include <math.h>

// ---------------- problem constants ----------------
#define D_MODEL 1024
#define DFF_DIM 4096
#define NTOK    2048          // B*S = 2*1024
#define NHEAD   16
#define DH      64
#define NLAYER  3
#define NCHUNK  16            // chunks per sequence
#define CLEN    64            // tokens per chunk

// ---------------- scratch (no allocs allowed) ----------------
__device__ float g_cur[NTOK * D_MODEL];
__device__ float g_q  [NTOK * D_MODEL];
__device__ float g_k  [NTOK * D_MODEL];
__device__ float g_v  [NTOK * D_MODEL];
__device__ float g_qf [NTOK * D_MODEL];
__device__ float g_kf [NTOK * D_MODEL];
__device__ float g_h  [NTOK * D_MODEL];
__device__ float g_hr [NTOK * D_MODEL];      // tf32-rounded h (FFN1 input)
__device__ float g_xr [NTOK * D_MODEL];      // tf32-rounded activation (QKV input)
__device__ float g_ffn[NTOK * DFF_DIM];
__device__ float g_S  [32 * NCHUNK * DH * DH];
__device__ float g_Z  [32 * NCHUNK * DH];
// tf32-rounded weights
__device__ float g_wqr[NLAYER * D_MODEL * D_MODEL];
__device__ float g_wkr[NLAYER * D_MODEL * D_MODEL];
__device__ float g_wvr[NLAYER * D_MODEL * D_MODEL];
__device__ float g_wor[NLAYER * D_MODEL * D_MODEL];
__device__ float g_w1r[NLAYER * D_MODEL * DFF_DIM];
__device__ float g_w2r[NLAYER * D_MODEL * DFF_DIM];

// ================= helpers =================
__device__ __forceinline__ uint32_t f2tf32(float f) {
    uint32_t u;
    asm("cvt.rna.tf32.f32 %0, %1;" : "=r"(u) : "f"(f));
    return u;
}
__device__ __forceinline__ float roundtf(float f) {
    return __uint_as_float(f2tf32(f));
}
__device__ __forceinline__ uint32_t smem_u32(const void* p) {
    uint32_t a;
    asm("{ .reg .u64 t; cvta.to.shared.u64 t, %1; cvt.u32.u64 %0, t; }" : "=r"(a) : "l"(p));
    return a;
}
__device__ __forceinline__ void mma_tf32(float c[4], uint32_t a0, uint32_t a1,
                                         uint32_t a2, uint32_t a3,
                                         uint32_t b0, uint32_t b1) {
    asm volatile(
        "mma.sync.aligned.m16n8k8.row.col.f32.tf32.tf32.f32 "
        "{%0,%1,%2,%3}, {%4,%5,%6,%7}, {%8,%9}, {%0,%1,%2,%3};"
        : "+f"(c[0]), "+f"(c[1]), "+f"(c[2]), "+f"(c[3])
        : "r"(a0), "r"(a1), "r"(a2), "r"(a3), "r"(b0), "r"(b1));
}
#define CP16(dst, src) \
    asm volatile("cp.async.cg.shared.global [%0], [%1], 16;" :: "r"(dst), "l"(src) : "memory")
#define CP_COMMIT() asm volatile("cp.async.commit_group;" ::: "memory")
#define CP_WAIT0()  asm volatile("cp.async.wait_group 0;" ::: "memory")

// ---------------- tf32 rounding copy (weights / x) ----------------
__global__ void round_kernel(const float* __restrict__ src, float* __restrict__ dst, int n4)
{
    int i = blockIdx.x * blockDim.x + threadIdx.x;
    if (i < n4) {
        float4 v = ((const float4*)src)[i];
        uint4 u;
        u.x = f2tf32(v.x); u.y = f2tf32(v.y);
        u.z = f2tf32(v.z); u.w = f2tf32(v.w);
        ((uint4*)dst)[i] = u;
    }
}

// ================= TF32 tensor-core GEMM — cp.async staging =================
// Inputs (A and B) are pre-rounded to tf32 bit patterns, so staging is a raw copy.
#define BK      64
#define ASTRIDE 68
#define BSTRIDE 168
#define ABUF (128 * ASTRIDE)
#define BBUF (64 * BSTRIDE)
#define GEMM_SMEM ((2 * ABUF + 2 * BBUF) * 4)

__global__ __launch_bounds__(512, 1) void mma_gemm(
    const float* __restrict__ A,
    const float* __restrict__ B0, const float* __restrict__ B1, const float* __restrict__ B2,
    const float* __restrict__ bias0, const float* __restrict__ bias1, const float* __restrict__ bias2,
    float* __restrict__ C0, float* __restrict__ C1, float* __restrict__ C2,
    int M, int N, int K, int do_relu)
{
    extern __shared__ float sm[];
    const uint32_t smb = smem_u32(sm);

    const int z = blockIdx.z;
    const float* B    = (z == 0) ? B0 : (z == 1) ? B1 : B2;
    const float* bias = (z == 0) ? bias0 : (z == 1) ? bias1 : bias2;
    float* C          = (z == 0) ? C0 : (z == 1) ? C1 : C2;

    const int tid  = threadIdx.x;
    const int bm   = blockIdx.y * 128;
    const int bn   = blockIdx.x * 128;
    const int lane = tid & 31;
    const int warp = tid >> 5;          // 0..15
    const int g    = lane >> 2;
    const int t    = lane & 3;
    const int m0   = (warp & 3) * 32;
    const int n0   = (warp >> 2) * 32;

    float acc[2][4][4];
    #pragma unroll
    for (int i = 0; i < 2; i++)
        #pragma unroll
        for (int j = 0; j < 4; j++)
            #pragma unroll
            for (int e = 0; e < 4; e++) acc[i][j][e] = 0.f;

    // staging indices (512 threads stage one 32-wide half as 2x16B per operand)
    const int ar = tid >> 2;              // 0..127
    const int ac = (tid & 3) * 8;         // 0,8,16,24
    const int br = tid >> 4;              // 0..31
    const int bc = (tid & 15) * 8;        // 0..120
    const int bcp = bc + ((bc >> 5) << 2);

    const float* Abase = A + (size_t)(bm + ar) * K + ac;
    const float* Bbase = B + (size_t)br * N + bn + bc;
    const uint32_t aoff = 4u * (uint32_t)(ar * ASTRIDE + ac);
    const uint32_t boff = 4u * (uint32_t)(br * BSTRIDE + bcp);

    int cnp[4];
    #pragma unroll
    for (int nf = 0; nf < 4; nf++) {
        const int cb = n0 + nf * 8;
        cnp[nf] = cb + ((cb >> 5) << 2) + g;
    }

    const int NC = K / BK;

    // issue all 8 cp.asyncs for chunk k0 into buffer `buf`
    auto issue_chunk = [&](int buf, int k0) {
        #pragma unroll
        for (int half = 0; half < 2; half++) {
            const int koff = half * 32;
            const float* asrc = Abase + k0 + koff;
            uint32_t adst = smb + 4u * (uint32_t)(buf * ABUF) + aoff + 4u * (uint32_t)koff;
            CP16(adst, asrc);
            CP16(adst + 16u, asrc + 4);
            const float* bsrc = Bbase + (size_t)(k0 + koff) * N;
            uint32_t bdst = smb + 4u * (uint32_t)(2 * ABUF + buf * BBUF)
                          + boff + 4u * (uint32_t)(koff * BSTRIDE);
            CP16(bdst, bsrc);
            CP16(bdst + 16u, bsrc + 4);
        }
    };

    // prologue
    issue_chunk(0, 0);
    CP_COMMIT();
    CP_WAIT0();
    __syncthreads();

    for (int c = 0; c < NC; c++) {
        const int buf = c & 1;
        const bool more = (c + 1 < NC);
        if (more) {
            issue_chunk(buf ^ 1, (c + 1) * BK);
            CP_COMMIT();
        }

        const uint32_t* Au = (const uint32_t*)(sm + buf * ABUF);
        const uint32_t* Bu = (const uint32_t*)(sm + 2 * ABUF + buf * BBUF);

        #pragma unroll
        for (int ks = 0; ks < 8; ks++) {
            const int kk = ks * 8;
            uint32_t af[2][4];
            #pragma unroll
            for (int mf = 0; mf < 2; mf++) {
                const int r = m0 + mf * 16 + g;
                af[mf][0] = Au[r * ASTRIDE + kk + t];
                af[mf][1] = Au[(r + 8) * ASTRIDE + kk + t];
                af[mf][2] = Au[r * ASTRIDE + kk + t + 4];
                af[mf][3] = Au[(r + 8) * ASTRIDE + kk + t + 4];
            }
            #pragma unroll
            for (int nf = 0; nf < 4; nf++) {
                uint32_t b0 = Bu[(kk + t) * BSTRIDE + cnp[nf]];
                uint32_t b1 = Bu[(kk + t + 4) * BSTRIDE + cnp[nf]];
                #pragma unroll
                for (int mf = 0; mf < 2; mf++)
                    mma_tf32(acc[mf][nf], af[mf][0], af[mf][1], af[mf][2], af[mf][3], b0, b1);
            }
        }

        if (more) {
            CP_WAIT0();
            __syncthreads();
        }
    }

    #pragma unroll
    for (int mf = 0; mf < 2; mf++) {
        const int r0 = bm + m0 + mf * 16 + g;
        #pragma unroll
        for (int nf = 0; nf < 4; nf++) {
            const int col = bn + n0 + nf * 8 + 2 * t;
            const float b0 = bias[col], b1 = bias[col + 1];
            float2 o0, o1;
            o0.x = acc[mf][nf][0] + b0; o0.y = acc[mf][nf][1] + b1;
            o1.x = acc[mf][nf][2] + b0; o1.y = acc[mf][nf][3] + b1;
            if (do_relu) {
                // FFN1 path: relu + tf32-round (output feeds FFN2's A operand)
                o0.x = roundtf(fmaxf(o0.x, 0.f)); o0.y = roundtf(fmaxf(o0.y, 0.f));
                o1.x = roundtf(fmaxf(o1.x, 0.f)); o1.y = roundtf(fmaxf(o1.y, 0.f));
            }
            *(float2*)(C + (size_t)r0 * N + col)       = o0;
            *(float2*)(C + (size_t)(r0 + 8) * N + col) = o1;
        }
    }
}

// ---------------- FAVOR feature map (fused q/k via blockIdx.y) ----------------
__global__ __launch_bounds__(256) void favor_kernel(
    const float* __restrict__ X0, const float* __restrict__ X1,
    const float* __restrict__ omega,
    float* __restrict__ P0, float* __restrict__ P1)
{
    __shared__ float om[DH * 32];
    __shared__ float xsb[8][DH];

    const float* X = blockIdx.y ? X1 : X0;
    float* Phi     = blockIdx.y ? P1 : P0;

    const int tid = threadIdx.x;
    for (int i = tid; i < DH * 32; i += 256) om[i] = omega[i];

    const int w    = tid >> 5;
    const int lane = tid & 31;
    const int gw   = blockIdx.x * 8 + w;
    const int token = gw >> 4;
    const int head  = gw & 15;

    const float scale = 0.35355339059327373f;   // 64^-0.25
    const size_t base = (size_t)token * D_MODEL + head * DH;

    float x0 = X[base + lane]      * scale;
    float x1 = X[base + 32 + lane] * scale;
    xsb[w][lane]      = x0;
    xsb[w][lane + 32] = x1;

    float hh = x0 * x0 + x1 * x1;
    #pragma unroll
    for (int o = 16; o; o >>= 1) hh += __shfl_xor_sync(0xffffffffu, hh, o);
    hh *= 0.5f;

    __syncthreads();

    float u = 0.f;
    #pragma unroll
    for (int d = 0; d < DH; d++)
        u = fmaf(xsb[w][d], om[d * 32 + lane], u);

    const float c = 0.125f;   // 64^-0.5
    Phi[base + lane]      = expf(u  - hh) * c;
    Phi[base + 32 + lane] = expf(-u - hh) * c;
}

// ============ chunked causal linear attention (token-parallel) ============
#define CST 68   // smem tile stride (words)

__device__ __forceinline__ void load_tile(
    float* dst, const float* __restrict__ src, size_t gbase, int tid)
{
    const int t = tid >> 2;
    const int qo = (tid & 3) * 16;
    const float* p = src + gbase + (size_t)t * D_MODEL + qo;
    float* d = dst + t * CST + qo;
    #pragma unroll
    for (int i = 0; i < 4; i++)
        *(float4*)(d + i * 4) = *(const float4*)(p + i * 4);
}

// Phase 1: S_c[m][d] = sum_t k[t][m] v[t][d] ; z_c[m] = sum_t k[t][m]
__global__ __launch_bounds__(256) void chunk_sums_kernel(
    const float* __restrict__ Kf, const float* __restrict__ V,
    float* __restrict__ gS, float* __restrict__ gZ)
{
    __shared__ float ks[64 * CST];
    __shared__ float vs[64 * CST];

    const int ch = blockIdx.x;
    const int bh = blockIdx.y;
    const int tid = threadIdx.x;
    const int b = bh >> 4, hd = bh & 15;
    const size_t gbase = (size_t)b * 1024 * D_MODEL + (size_t)(ch * CLEN) * D_MODEL + hd * DH;

    load_tile(ks, Kf, gbase, tid);
    load_tile(vs, V,  gbase, tid);
    __syncthreads();

    const int mg = (tid >> 4) * 4;
    const int dg = (tid & 15) * 4;

    float acc[4][4];
    float zz[4];
    #pragma unroll
    for (int e = 0; e < 4; e++) {
        zz[e] = 0.f;
        #pragma unroll
        for (int c = 0; c < 4; c++) acc[e][c] = 0.f;
    }

    #pragma unroll 4
    for (int t = 0; t < CLEN; t++) {
        float4 v4 = *(const float4*)(vs + t * CST + dg);
        #pragma unroll
        for (int e = 0; e < 4; e++) {
            const float kv = ks[t * CST + mg + e];
            zz[e] += kv;
            acc[e][0] = fmaf(kv, v4.x, acc[e][0]);
            acc[e][1] = fmaf(kv, v4.y, acc[e][1]);
            acc[e][2] = fmaf(kv, v4.z, acc[e][2]);
            acc[e][3] = fmaf(kv, v4.w, acc[e][3]);
        }
    }

    const size_t idx = (size_t)(bh * NCHUNK + ch);
    #pragma unroll
    for (int e = 0; e < 4; e++)
        *(float4*)(gS + idx * 4096 + (size_t)(mg + e) * 64 + dg) =
            make_float4(acc[e][0], acc[e][1], acc[e][2], acc[e][3]);
    if ((tid & 15) == 0) {
        #pragma unroll
        for (int e = 0; e < 4; e++) gZ[idx * 64 + mg + e] = zz[e];
    }
}

// Phase 2: exclusive prefix over 16 chunks — one thread per (bh, element).
__global__ __launch_bounds__(256) void chunk_prefix_kernel(
    float* __restrict__ gS, float* __restrict__ gZ)
{
    const int gid = blockIdx.x * 256 + threadIdx.x;   // 0 .. 131071
    const int bh = gid >> 12;
    const int e  = gid & 4095;

    const size_t base = (size_t)bh * (NCHUNK * 4096) + e;
    float vals[NCHUNK];
    #pragma unroll
    for (int ch = 0; ch < NCHUNK; ch++)
        vals[ch] = gS[base + (size_t)ch * 4096];

    float run = 0.f;
    #pragma unroll
    for (int ch = 0; ch < NCHUNK; ch++) {
        const float t = vals[ch];
        gS[base + (size_t)ch * 4096] = run;
        run += t;
    }

    if (e < 64) {
        const size_t zbase = (size_t)bh * (NCHUNK * 64) + e;
        float zv[NCHUNK];
        #pragma unroll
        for (int ch = 0; ch < NCHUNK; ch++)
            zv[ch] = gZ[zbase + ch * 64];
        float zr = 0.f;
        #pragma unroll
        for (int ch = 0; ch < NCHUNK; ch++) {
            const float t = zv[ch];
            gZ[zbase + ch * 64] = zr;
            zr += t;
        }
    }
}

// Phase 3: token-parallel intra-chunk attention (output tf32-rounded: feeds Wo GEMM).
__global__ __launch_bounds__(256) void chunk_attn_kernel(
    const float* __restrict__ Qf, const float* __restrict__ Kf,
    const float* __restrict__ V, const float* __restrict__ gS,
    const float* __restrict__ gZ, float* __restrict__ Out)
{
    extern __shared__ float smw[];
    float* qs = smw;                 // [i][m]
    float* kt = smw + 64 * CST;      // [m][j]
    float* vs = smw + 2 * 64 * CST;  // [j][d]
    float* Sp = smw + 3 * 64 * CST;  // [m][d]
    float* Am = smw + 4 * 64 * CST;  // [i][j]
    float* zp = smw + 5 * 64 * CST;  // [m]

    const int ch = blockIdx.x;
    const int bh = blockIdx.y;
    const int tid = threadIdx.x;
    const int b = bh >> 4, hd = bh & 15;
    const size_t gbase = (size_t)b * 1024 * D_MODEL + (size_t)(ch * CLEN) * D_MODEL + hd * DH;
    const size_t idx = (size_t)(bh * NCHUNK + ch);

    load_tile(qs, Qf, gbase, tid);
    load_tile(vs, V,  gbase, tid);
    {
        const int t = tid >> 2;
        const int qo = (tid & 3) * 16;
        const float* p = Kf + gbase + (size_t)t * D_MODEL + qo;
        #pragma unroll
        for (int i = 0; i < 16; i += 4) {
            float4 kv = *(const float4*)(p + i);
            kt[(qo + i + 0) * CST + t] = kv.x;
            kt[(qo + i + 1) * CST + t] = kv.y;
            kt[(qo + i + 2) * CST + t] = kv.z;
            kt[(qo + i + 3) * CST + t] = kv.w;
        }
    }
    {
        const int m = tid >> 2;
        const int qo = (tid & 3) * 16;
        const float* p = gS + idx * 4096 + (size_t)m * 64 + qo;
        float* dp = Sp + m * CST + qo;
        #pragma unroll
        for (int i = 0; i < 4; i++)
            *(float4*)(dp + i * 4) = *(const float4*)(p + i * 4);
    }
    if (tid < 64) zp[tid] = gZ[idx * 64 + tid];
    __syncthreads();

    const int ig = (tid >> 4) * 4;
    const int jg = (tid & 15) * 4;

    float a[4][4];
    float qz[4];
    #pragma unroll
    for (int e = 0; e < 4; e++) {
        qz[e] = 0.f;
        #pragma unroll
        for (int c = 0; c < 4; c++) a[e][c] = 0.f;
    }
    #pragma unroll 4
    for (int m = 0; m < DH; m++) {
        const float zv = zp[m];
        float4 k4 = *(const float4*)(kt + m * CST + jg);
        #pragma unroll
        for (int e = 0; e < 4; e++) {
            const float qv = qs[(ig + e) * CST + m];
            qz[e] = fmaf(qv, zv, qz[e]);
            a[e][0] = fmaf(qv, k4.x, a[e][0]);
            a[e][1] = fmaf(qv, k4.y, a[e][1]);
            a[e][2] = fmaf(qv, k4.z, a[e][2]);
            a[e][3] = fmaf(qv, k4.w, a[e][3]);
        }
    }
    float den[4];
    #pragma unroll
    for (int e = 0; e < 4; e++) {
        const int i = ig + e;
        #pragma unroll
        for (int c = 0; c < 4; c++)
            if (jg + c > i) a[e][c] = 0.f;
        float rs = a[e][0] + a[e][1] + a[e][2] + a[e][3];
        rs += __shfl_xor_sync(0xffffffffu, rs, 1);
        rs += __shfl_xor_sync(0xffffffffu, rs, 2);
        rs += __shfl_xor_sync(0xffffffffu, rs, 4);
        rs += __shfl_xor_sync(0xffffffffu, rs, 8);
        den[e] = qz[e] + rs + 1e-6f;
        *(float4*)(Am + i * CST + jg) = make_float4(a[e][0], a[e][1], a[e][2], a[e][3]);
    }
    __syncthreads();

    float acc[4][4];
    #pragma unroll
    for (int e = 0; e < 4; e++)
        #pragma unroll
        for (int c = 0; c < 4; c++) acc[e][c] = 0.f;

    #pragma unroll 4
    for (int m = 0; m < DH; m++) {
        float4 s4 = *(const float4*)(Sp + m * CST + jg);
        #pragma unroll
        for (int e = 0; e < 4; e++) {
            const float qv = qs[(ig + e) * CST + m];
            acc[e][0] = fmaf(qv, s4.x, acc[e][0]);
            acc[e][1] = fmaf(qv, s4.y, acc[e][1]);
            acc[e][2] = fmaf(qv, s4.z, acc[e][2]);
            acc[e][3] = fmaf(qv, s4.w, acc[e][3]);
        }
    }
    const int jmax = ig + 3;
    for (int j = 0; j <= jmax; j++) {
        float4 v4 = *(const float4*)(vs + j * CST + jg);
        #pragma unroll
        for (int e = 0; e < 4; e++) {
            const float av = Am[(ig + e) * CST + j];
            acc[e][0] = fmaf(av, v4.x, acc[e][0]);
            acc[e][1] = fmaf(av, v4.y, acc[e][1]);
            acc[e][2] = fmaf(av, v4.z, acc[e][2]);
            acc[e][3] = fmaf(av, v4.w, acc[e][3]);
        }
    }

    #pragma unroll
    for (int e = 0; e < 4; e++) {
        const float inv = 1.f / den[e];
        float* op = Out + gbase + (size_t)(ig + e) * D_MODEL + jg;
        *(float4*)op = make_float4(roundtf(acc[e][0] * inv), roundtf(acc[e][1] * inv),
                                   roundtf(acc[e][2] * inv), roundtf(acc[e][3] * inv));
    }
}
#define ATTN_SMEM ((5 * 64 * CST + 64) * 4)

// ---------------- LayerNorm: out = LN(a + r) * g + b ; optional rounded copy ----------------
__global__ __launch_bounds__(256) void ln_kernel(
    float* __restrict__ out, const float* __restrict__ a,
    const float* __restrict__ r, const float* __restrict__ gam,
    const float* __restrict__ bet, float* __restrict__ outr)
{
    const int row = blockIdx.x;
    const int tid = threadIdx.x;
    const float* pa = a + (size_t)row * D_MODEL;
    const float* pr = r + (size_t)row * D_MODEL;

    float v[4];
    float s = 0.f, ss = 0.f;
    #pragma unroll
    for (int i = 0; i < 4; i++) {
        int idx = tid + i * 256;
        float t = pa[idx] + pr[idx];
        v[i] = t; s += t; ss = fmaf(t, t, ss);
    }

    __shared__ float red[18];
    #pragma unroll
    for (int o = 16; o; o >>= 1) {
        s  += __shfl_xor_sync(0xffffffffu, s,  o);
        ss += __shfl_xor_sync(0xffffffffu, ss, o);
    }
    const int w = tid >> 5, lane = tid & 31;
    __shared__ float rw[16];
    if (lane == 0) { rw[w] = s; rw[w + 8] = ss; }
    __syncthreads();
    if (tid == 0) {
        float S0 = 0.f, S1 = 0.f;
        #pragma unroll
        for (int i = 0; i < 8; i++) { S0 += rw[i]; S1 += rw[i + 8]; }
        red[16] = S0; red[17] = S1;
    }
    __syncthreads();

    const float mean = red[16] * (1.f / 1024.f);
    const float var  = red[17] * (1.f / 1024.f) - mean * mean;
    const float inv  = rsqrtf(var + 1e-5f);

    float* po = out + (size_t)row * D_MODEL;
    float* pq = (outr != nullptr) ? outr + (size_t)row * D_MODEL : nullptr;
    #pragma unroll
    for (int i = 0; i < 4; i++) {
        int idx = tid + i * 256;
        float o = (v[i] - mean) * inv * gam[idx] + bet[idx];
        po[idx] = o;
        if (pq) pq[idx] = roundtf(o);
    }
}

// ---------------- launch ----------------
extern "C" void kernel_launch(void* const* d_in, const int* in_sizes, int n_in,
                              void* d_out, int out_size)
{
    const float* x    = (const float*)d_in[0];
    const float* Wq   = (const float*)d_in[1];
    const float* bq   = (const float*)d_in[2];
    const float* Wk   = (const float*)d_in[3];
    const float* bk   = (const float*)d_in[4];
    const float* Wv   = (const float*)d_in[5];
    const float* bv   = (const float*)d_in[6];
    const float* Wo   = (const float*)d_in[7];
    const float* bo   = (const float*)d_in[8];
    const float* omg  = (const float*)d_in[9];
    const float* ln1g = (const float*)d_in[10];
    const float* ln1b = (const float*)d_in[11];
    const float* ln2g = (const float*)d_in[12];
    const float* ln2b = (const float*)d_in[13];
    const float* W1   = (const float*)d_in[14];
    const float* bf1  = (const float*)d_in[15];
    const float* W2   = (const float*)d_in[16];
    const float* bf2  = (const float*)d_in[17];
    float* out = (float*)d_out;

    float *cur, *q, *k, *v, *qf, *kf, *h, *hr, *xr, *ffn, *gS, *gZ;
    float *wqr, *wkr, *wvr, *wor, *w1r, *w2r;
    cudaGetSymbolAddress((void**)&cur, g_cur);
    cudaGetSymbolAddress((void**)&q,   g_q);
    cudaGetSymbolAddress((void**)&k,   g_k);
    cudaGetSymbolAddress((void**)&v,   g_v);
    cudaGetSymbolAddress((void**)&qf,  g_qf);
    cudaGetSymbolAddress((void**)&kf,  g_kf);
    cudaGetSymbolAddress((void**)&h,   g_h);
    cudaGetSymbolAddress((void**)&hr,  g_hr);
    cudaGetSymbolAddress((void**)&xr,  g_xr);
    cudaGetSymbolAddress((void**)&ffn, g_ffn);
    cudaGetSymbolAddress((void**)&gS,  g_S);
    cudaGetSymbolAddress((void**)&gZ,  g_Z);
    cudaGetSymbolAddress((void**)&wqr, g_wqr);
    cudaGetSymbolAddress((void**)&wkr, g_wkr);
    cudaGetSymbolAddress((void**)&wvr, g_wvr);
    cudaGetSymbolAddress((void**)&wor, g_wor);
    cudaGetSymbolAddress((void**)&w1r, g_w1r);
    cudaGetSymbolAddress((void**)&w2r, g_w2r);

    cudaFuncSetAttribute(mma_gemm, cudaFuncAttributeMaxDynamicSharedMemorySize, GEMM_SMEM);
    cudaFuncSetAttribute(chunk_attn_kernel, cudaFuncAttributeMaxDynamicSharedMemorySize, ATTN_SMEM);

    // -------- prep: tf32-round all GEMM operand sources --------
    const int nDD4 = NLAYER * D_MODEL * D_MODEL / 4;   // 786432
    const int nDF4 = NLAYER * D_MODEL * DFF_DIM / 4;   // 3145728
    const int nX4  = NTOK * D_MODEL / 4;               // 524288
    round_kernel<<<nDD4 / 256, 256>>>(Wq, wqr, nDD4);
    round_kernel<<<nDD4 / 256, 256>>>(Wk, wkr, nDD4);
    round_kernel<<<nDD4 / 256, 256>>>(Wv, wvr, nDD4);
    round_kernel<<<nDD4 / 256, 256>>>(Wo, wor, nDD4);
    round_kernel<<<nDF4 / 256, 256>>>(W1, w1r, nDF4);
    round_kernel<<<nDF4 / 256, 256>>>(W2, w2r, nDF4);
    round_kernel<<<nX4  / 256, 256>>>(x,  xr,  nX4);

    const dim3 gQKV(D_MODEL / 128, NTOK / 128, 3);
    const dim3 gD(D_MODEL / 128, NTOK / 128, 1);
    const dim3 gF(DFF_DIM / 128, NTOK / 128, 1);
    const dim3 gCh(NCHUNK, 32);
    const dim3 gFav(NTOK * NHEAD / 8, 2);
    const int  gPref = (32 * 4096) / 256;

    for (int l = 0; l < NLAYER; l++) {
        const size_t wDD  = (size_t)l * D_MODEL * D_MODEL;
        const size_t wDF  = (size_t)l * D_MODEL * DFF_DIM;
        const size_t bD   = (size_t)l * D_MODEL;
        const size_t bF   = (size_t)l * DFF_DIM;
        const size_t oOff = (size_t)l * DH * 32;
        const float* resA = (l == 0) ? x : cur;   // raw residual input

        mma_gemm<<<gQKV, 512, GEMM_SMEM>>>(xr,
            wqr + wDD, wkr + wDD, wvr + wDD,
            bq + bD, bk + bD, bv + bD,
            q, k, v, NTOK, D_MODEL, D_MODEL, 0);

        favor_kernel<<<gFav, 256>>>(q, k, omg + oOff, qf, kf);

        chunk_sums_kernel<<<gCh, 256>>>(kf, v, gS, gZ);
        chunk_prefix_kernel<<<gPref, 256>>>(gS, gZ);
        chunk_attn_kernel<<<gCh, 256, ATTN_SMEM>>>(qf, kf, v, gS, gZ, q);  // attn -> q (rounded)

        mma_gemm<<<gD, 512, GEMM_SMEM>>>(q,
            wor + wDD, wor + wDD, wor + wDD,
            bo + bD, bo + bD, bo + bD,
            k, k, k, NTOK, D_MODEL, D_MODEL, 0);
        ln_kernel<<<NTOK, 256>>>(h, resA, k, ln1g + bD, ln1b + bD, hr);

        mma_gemm<<<gF, 512, GEMM_SMEM>>>(hr,
            w1r + wDF, w1r + wDF, w1r + wDF,
            bf1 + bF, bf1 + bF, bf1 + bF,
            ffn, ffn, ffn, NTOK, DFF_DIM, D_MODEL, 1);
        mma_gemm<<<gD, 512, GEMM_SMEM>>>(ffn,
            w2r + wDF, w2r + wDF, w2r + wDF,
            bf2 + bD, bf2 + bD, bf2 + bD,
            v, v, v, NTOK, D_MODEL, DFF_DIM, 0);

        const bool last = (l == NLAYER - 1);
        float* dst = last ? out : cur;
        ln_kernel<<<NTOK, 256>>>(dst, h, v, ln2g + bD, ln2b + bD, last ? nullptr : xr);
    }
}

// round 12
// speedup vs baseline: 1.0270x; 1.0270x over previous
#include <cuda_runtime.h>
#include <cstdint>
#include <math.h>

// ---------------- problem constants ----------------
#define D_MODEL 1024
#define DFF_DIM 4096
#define NTOK    2048          // B*S = 2*1024
#define NHEAD   16
#define DH      64
#define NLAYER  3
#define NCHUNK  16            // chunks per sequence
#define CLEN    64            // tokens per chunk

// ---------------- scratch (no allocs allowed) ----------------
__device__ float g_cur[NTOK * D_MODEL];
__device__ float g_q  [NTOK * D_MODEL];
__device__ float g_k  [NTOK * D_MODEL];
__device__ float g_v  [NTOK * D_MODEL];
__device__ float g_qf [NTOK * D_MODEL];
__device__ float g_kf [NTOK * D_MODEL];
__device__ float g_h  [NTOK * D_MODEL];
__device__ float g_hr [NTOK * D_MODEL];      // tf32-rounded h (FFN1 A operand)
__device__ float g_xr [NTOK * D_MODEL];      // tf32-rounded activation (QKV A operand)
__device__ float g_ffn[NTOK * DFF_DIM];
__device__ float g_S  [32 * NCHUNK * DH * DH];
__device__ float g_Z  [32 * NCHUNK * DH];

// ================= helpers =================
__device__ __forceinline__ uint32_t f2tf32(float f) {
    uint32_t u;
    asm("cvt.rna.tf32.f32 %0, %1;" : "=r"(u) : "f"(f));
    return u;
}
__device__ __forceinline__ float roundtf(float f) {
    return __uint_as_float(f2tf32(f));
}
__device__ __forceinline__ uint32_t smem_u32(const void* p) {
    uint32_t a;
    asm("{ .reg .u64 t; cvta.to.shared.u64 t, %1; cvt.u32.u64 %0, t; }" : "=r"(a) : "l"(p));
    return a;
}
__device__ __forceinline__ void mma_tf32(float c[4], uint32_t a0, uint32_t a1,
                                         uint32_t a2, uint32_t a3,
                                         uint32_t b0, uint32_t b1) {
    asm volatile(
        "mma.sync.aligned.m16n8k8.row.col.f32.tf32.tf32.f32 "
        "{%0,%1,%2,%3}, {%4,%5,%6,%7}, {%8,%9}, {%0,%1,%2,%3};"
        : "+f"(c[0]), "+f"(c[1]), "+f"(c[2]), "+f"(c[3])
        : "r"(a0), "r"(a1), "r"(a2), "r"(a3), "r"(b0), "r"(b1));
}
#define CP16(dst, src) \
    asm volatile("cp.async.cg.shared.global [%0], [%1], 16;" :: "r"(dst), "l"(src) : "memory")
#define CP_COMMIT() asm volatile("cp.async.commit_group;" ::: "memory")
#define CP_WAIT0()  asm volatile("cp.async.wait_group 0;" ::: "memory")

// ---------------- tf32 rounding copy (layer-0 x only) ----------------
__global__ void round_kernel(const float* __restrict__ src, float* __restrict__ dst, int n4)
{
    int i = blockIdx.x * blockDim.x + threadIdx.x;
    if (i < n4) {
        float4 v = ((const float4*)src)[i];
        uint4 u;
        u.x = f2tf32(v.x); u.y = f2tf32(v.y);
        u.z = f2tf32(v.z); u.w = f2tf32(v.w);
        ((uint4*)dst)[i] = u;
    }
}

// ================= TF32 tensor-core GEMM — hybrid staging =================
// A (activations, pre-rounded): cp.async raw copy.
// B (weights, raw fp32): LDG -> cvt.rna.tf32 -> STS (proven conflict-free layout).
#define BK      64
#define ASTRIDE 68
#define BSTRIDE 168
#define ABUF (128 * ASTRIDE)
#define BBUF (64 * BSTRIDE)
#define GEMM_SMEM ((2 * ABUF + 2 * BBUF) * 4)

__global__ __launch_bounds__(512, 1) void mma_gemm(
    const float* __restrict__ A,
    const float* __restrict__ B0, const float* __restrict__ B1, const float* __restrict__ B2,
    const float* __restrict__ bias0, const float* __restrict__ bias1, const float* __restrict__ bias2,
    float* __restrict__ C0, float* __restrict__ C1, float* __restrict__ C2,
    int M, int N, int K, int do_relu)
{
    extern __shared__ float sm[];
    const uint32_t smb = smem_u32(sm);

    const int z = blockIdx.z;
    const float* B    = (z == 0) ? B0 : (z == 1) ? B1 : B2;
    const float* bias = (z == 0) ? bias0 : (z == 1) ? bias1 : bias2;
    float* C          = (z == 0) ? C0 : (z == 1) ? C1 : C2;

    const int tid  = threadIdx.x;
    const int bm   = blockIdx.y * 128;
    const int bn   = blockIdx.x * 128;
    const int lane = tid & 31;
    const int warp = tid >> 5;          // 0..15
    const int g    = lane >> 2;
    const int t    = lane & 3;
    const int m0   = (warp & 3) * 32;
    const int n0   = (warp >> 2) * 32;

    float acc[2][4][4];
    #pragma unroll
    for (int i = 0; i < 2; i++)
        #pragma unroll
        for (int j = 0; j < 4; j++)
            #pragma unroll
            for (int e = 0; e < 4; e++) acc[i][j][e] = 0.f;

    // staging indices (512 threads, one 32-wide K half)
    const int ar = tid >> 2;              // 0..127
    const int ac = (tid & 3) * 8;         // 0,8,16,24
    const int br = tid >> 4;              // 0..31
    const int bc = (tid & 15) * 8;        // 0..120
    const int bcp = bc + ((bc >> 5) << 2);

    const float* Abase = A + (size_t)(bm + ar) * K + ac;
    const float* Bbase = B + (size_t)br * N + bn + bc;
    const uint32_t aoff = 4u * (uint32_t)(ar * ASTRIDE + ac);

    int cnp[4];
    #pragma unroll
    for (int nf = 0; nf < 4; nf++) {
        const int cb = n0 + nf * 8;
        cnp[nf] = cb + ((cb >> 5) << 2) + g;
    }

    const int NC = K / BK;

    // A: issue both halves of chunk k0 into buffer `buf` via cp.async
    auto issueA = [&](int buf, int k0) {
        #pragma unroll
        for (int half = 0; half < 2; half++) {
            const int koff = half * 32;
            const float* asrc = Abase + k0 + koff;
            uint32_t adst = smb + 4u * (uint32_t)(buf * ABUF) + aoff + 4u * (uint32_t)koff;
            CP16(adst, asrc);
            CP16(adst + 16u, asrc + 4);
        }
    };
    // B: load one 32-wide half into regs
    auto ldgB = [&](int k0, int koff, float4 pb[2]) {
        const float* bsrc = Bbase + (size_t)(k0 + koff) * N;
        pb[0] = *(const float4*)(bsrc);
        pb[1] = *(const float4*)(bsrc + 4);
    };
    // B: cvt + STS one half
    auto stsB = [&](float* Bd, int koff, const float4 pb[2]) {
        #pragma unroll
        for (int i = 0; i < 2; i++) {
            uint4 u;
            u.x = f2tf32(pb[i].x); u.y = f2tf32(pb[i].y);
            u.z = f2tf32(pb[i].z); u.w = f2tf32(pb[i].w);
            *(uint4*)(Bd + (koff + br) * BSTRIDE + bcp + i * 4) = u;
        }
    };

    // ---- prologue: chunk 0 ----
    issueA(0, 0);
    CP_COMMIT();
    {
        float4 pb[2];
        ldgB(0, 0, pb);  stsB(sm + 2 * ABUF, 0, pb);
        ldgB(0, 32, pb); stsB(sm + 2 * ABUF, 32, pb);
    }
    CP_WAIT0();
    __syncthreads();

    for (int c = 0; c < NC; c++) {
        const int buf = c & 1;
        const int nb  = buf ^ 1;
        const bool more = (c + 1 < NC);
        float* Bd = sm + 2 * ABUF + nb * BBUF;
        float4 pb[2];

        if (more) {
            issueA(nb, (c + 1) * BK);
            CP_COMMIT();
            ldgB((c + 1) * BK, 0, pb);
        }

        const uint32_t* Au = (const uint32_t*)(sm + buf * ABUF);
        const uint32_t* Bu = (const uint32_t*)(sm + 2 * ABUF + buf * BBUF);

        #pragma unroll
        for (int ks = 0; ks < 4; ks++) {
            const int kk = ks * 8;
            uint32_t af[2][4];
            #pragma unroll
            for (int mf = 0; mf < 2; mf++) {
                const int r = m0 + mf * 16 + g;
                af[mf][0] = Au[r * ASTRIDE + kk + t];
                af[mf][1] = Au[(r + 8) * ASTRIDE + kk + t];
                af[mf][2] = Au[r * ASTRIDE + kk + t + 4];
                af[mf][3] = Au[(r + 8) * ASTRIDE + kk + t + 4];
            }
            #pragma unroll
            for (int nf = 0; nf < 4; nf++) {
                uint32_t b0 = Bu[(kk + t) * BSTRIDE + cnp[nf]];
                uint32_t b1 = Bu[(kk + t + 4) * BSTRIDE + cnp[nf]];
                #pragma unroll
                for (int mf = 0; mf < 2; mf++)
                    mma_tf32(acc[mf][nf], af[mf][0], af[mf][1], af[mf][2], af[mf][3], b0, b1);
            }
        }

        if (more) {
            stsB(Bd, 0, pb);
            ldgB((c + 1) * BK, 32, pb);
        }

        #pragma unroll
        for (int ks = 4; ks < 8; ks++) {
            const int kk = ks * 8;
            uint32_t af[2][4];
            #pragma unroll
            for (int mf = 0; mf < 2; mf++) {
                const int r = m0 + mf * 16 + g;
                af[mf][0] = Au[r * ASTRIDE + kk + t];
                af[mf][1] = Au[(r + 8) * ASTRIDE + kk + t];
                af[mf][2] = Au[r * ASTRIDE + kk + t + 4];
                af[mf][3] = Au[(r + 8) * ASTRIDE + kk + t + 4];
            }
            #pragma unroll
            for (int nf = 0; nf < 4; nf++) {
                uint32_t b0 = Bu[(kk + t) * BSTRIDE + cnp[nf]];
                uint32_t b1 = Bu[(kk + t + 4) * BSTRIDE + cnp[nf]];
                #pragma unroll
                for (int mf = 0; mf < 2; mf++)
                    mma_tf32(acc[mf][nf], af[mf][0], af[mf][1], af[mf][2], af[mf][3], b0, b1);
            }
        }

        if (more) {
            stsB(Bd, 32, pb);
            CP_WAIT0();
            __syncthreads();
        }
    }

    #pragma unroll
    for (int mf = 0; mf < 2; mf++) {
        const int r0 = bm + m0 + mf * 16 + g;
        #pragma unroll
        for (int nf = 0; nf < 4; nf++) {
            const int col = bn + n0 + nf * 8 + 2 * t;
            const float b0 = bias[col], b1 = bias[col + 1];
            float2 o0, o1;
            o0.x = acc[mf][nf][0] + b0; o0.y = acc[mf][nf][1] + b1;
            o1.x = acc[mf][nf][2] + b0; o1.y = acc[mf][nf][3] + b1;
            if (do_relu) {
                // FFN1 path: relu + tf32-round (output feeds FFN2's A operand)
                o0.x = roundtf(fmaxf(o0.x, 0.f)); o0.y = roundtf(fmaxf(o0.y, 0.f));
                o1.x = roundtf(fmaxf(o1.x, 0.f)); o1.y = roundtf(fmaxf(o1.y, 0.f));
            }
            *(float2*)(C + (size_t)r0 * N + col)       = o0;
            *(float2*)(C + (size_t)(r0 + 8) * N + col) = o1;
        }
    }
}

// ---------------- FAVOR feature map (fused q/k via blockIdx.y) ----------------
__global__ __launch_bounds__(256) void favor_kernel(
    const float* __restrict__ X0, const float* __restrict__ X1,
    const float* __restrict__ omega,
    float* __restrict__ P0, float* __restrict__ P1)
{
    __shared__ float om[DH * 32];
    __shared__ float xsb[8][DH];

    const float* X = blockIdx.y ? X1 : X0;
    float* Phi     = blockIdx.y ? P1 : P0;

    const int tid = threadIdx.x;
    for (int i = tid; i < DH * 32; i += 256) om[i] = omega[i];

    const int w    = tid >> 5;
    const int lane = tid & 31;
    const int gw   = blockIdx.x * 8 + w;
    const int token = gw >> 4;
    const int head  = gw & 15;

    const float scale = 0.35355339059327373f;   // 64^-0.25
    const size_t base = (size_t)token * D_MODEL + head * DH;

    float x0 = X[base + lane]      * scale;
    float x1 = X[base + 32 + lane] * scale;
    xsb[w][lane]      = x0;
    xsb[w][lane + 32] = x1;

    float hh = x0 * x0 + x1 * x1;
    #pragma unroll
    for (int o = 16; o; o >>= 1) hh += __shfl_xor_sync(0xffffffffu, hh, o);
    hh *= 0.5f;

    __syncthreads();

    float u = 0.f;
    #pragma unroll
    for (int d = 0; d < DH; d++)
        u = fmaf(xsb[w][d], om[d * 32 + lane], u);

    const float c = 0.125f;   // 64^-0.5
    Phi[base + lane]      = expf(u  - hh) * c;
    Phi[base + 32 + lane] = expf(-u - hh) * c;
}

// ============ chunked causal linear attention (token-parallel) ============
#define CST 68   // smem tile stride (words)

__device__ __forceinline__ void load_tile(
    float* dst, const float* __restrict__ src, size_t gbase, int tid)
{
    const int t = tid >> 2;
    const int qo = (tid & 3) * 16;
    const float* p = src + gbase + (size_t)t * D_MODEL + qo;
    float* d = dst + t * CST + qo;
    #pragma unroll
    for (int i = 0; i < 4; i++)
        *(float4*)(d + i * 4) = *(const float4*)(p + i * 4);
}

// Phase 1: S_c[m][d] = sum_t k[t][m] v[t][d] ; z_c[m] = sum_t k[t][m]
__global__ __launch_bounds__(256) void chunk_sums_kernel(
    const float* __restrict__ Kf, const float* __restrict__ V,
    float* __restrict__ gS, float* __restrict__ gZ)
{
    __shared__ float ks[64 * CST];
    __shared__ float vs[64 * CST];

    const int ch = blockIdx.x;
    const int bh = blockIdx.y;
    const int tid = threadIdx.x;
    const int b = bh >> 4, hd = bh & 15;
    const size_t gbase = (size_t)b * 1024 * D_MODEL + (size_t)(ch * CLEN) * D_MODEL + hd * DH;

    load_tile(ks, Kf, gbase, tid);
    load_tile(vs, V,  gbase, tid);
    __syncthreads();

    const int mg = (tid >> 4) * 4;
    const int dg = (tid & 15) * 4;

    float acc[4][4];
    float zz[4];
    #pragma unroll
    for (int e = 0; e < 4; e++) {
        zz[e] = 0.f;
        #pragma unroll
        for (int c = 0; c < 4; c++) acc[e][c] = 0.f;
    }

    #pragma unroll 4
    for (int t = 0; t < CLEN; t++) {
        float4 v4 = *(const float4*)(vs + t * CST + dg);
        #pragma unroll
        for (int e = 0; e < 4; e++) {
            const float kv = ks[t * CST + mg + e];
            zz[e] += kv;
            acc[e][0] = fmaf(kv, v4.x, acc[e][0]);
            acc[e][1] = fmaf(kv, v4.y, acc[e][1]);
            acc[e][2] = fmaf(kv, v4.z, acc[e][2]);
            acc[e][3] = fmaf(kv, v4.w, acc[e][3]);
        }
    }

    const size_t idx = (size_t)(bh * NCHUNK + ch);
    #pragma unroll
    for (int e = 0; e < 4; e++)
        *(float4*)(gS + idx * 4096 + (size_t)(mg + e) * 64 + dg) =
            make_float4(acc[e][0], acc[e][1], acc[e][2], acc[e][3]);
    if ((tid & 15) == 0) {
        #pragma unroll
        for (int e = 0; e < 4; e++) gZ[idx * 64 + mg + e] = zz[e];
    }
}

// Phase 2: exclusive prefix over 16 chunks — one thread per (bh, element).
__global__ __launch_bounds__(256) void chunk_prefix_kernel(
    float* __restrict__ gS, float* __restrict__ gZ)
{
    const int gid = blockIdx.x * 256 + threadIdx.x;   // 0 .. 131071
    const int bh = gid >> 12;
    const int e  = gid & 4095;

    const size_t base = (size_t)bh * (NCHUNK * 4096) + e;
    float vals[NCHUNK];
    #pragma unroll
    for (int ch = 0; ch < NCHUNK; ch++)
        vals[ch] = gS[base + (size_t)ch * 4096];

    float run = 0.f;
    #pragma unroll
    for (int ch = 0; ch < NCHUNK; ch++) {
        const float t = vals[ch];
        gS[base + (size_t)ch * 4096] = run;
        run += t;
    }

    if (e < 64) {
        const size_t zbase = (size_t)bh * (NCHUNK * 64) + e;
        float zv[NCHUNK];
        #pragma unroll
        for (int ch = 0; ch < NCHUNK; ch++)
            zv[ch] = gZ[zbase + ch * 64];
        float zr = 0.f;
        #pragma unroll
        for (int ch = 0; ch < NCHUNK; ch++) {
            const float t = zv[ch];
            gZ[zbase + ch * 64] = zr;
            zr += t;
        }
    }
}

// Phase 3: token-parallel intra-chunk attention (output tf32-rounded: feeds Wo GEMM).
__global__ __launch_bounds__(256) void chunk_attn_kernel(
    const float* __restrict__ Qf, const float* __restrict__ Kf,
    const float* __restrict__ V, const float* __restrict__ gS,
    const float* __restrict__ gZ, float* __restrict__ Out)
{
    extern __shared__ float smw[];
    float* qs = smw;                 // [i][m]
    float* kt = smw + 64 * CST;      // [m][j]
    float* vs = smw + 2 * 64 * CST;  // [j][d]
    float* Sp = smw + 3 * 64 * CST;  // [m][d]
    float* Am = smw + 4 * 64 * CST;  // [i][j]
    float* zp = smw + 5 * 64 * CST;  // [m]

    const int ch = blockIdx.x;
    const int bh = blockIdx.y;
    const int tid = threadIdx.x;
    const int b = bh >> 4, hd = bh & 15;
    const size_t gbase = (size_t)b * 1024 * D_MODEL + (size_t)(ch * CLEN) * D_MODEL + hd * DH;
    const size_t idx = (size_t)(bh * NCHUNK + ch);

    load_tile(qs, Qf, gbase, tid);
    load_tile(vs, V,  gbase, tid);
    {
        const int t = tid >> 2;
        const int qo = (tid & 3) * 16;
        const float* p = Kf + gbase + (size_t)t * D_MODEL + qo;
        #pragma unroll
        for (int i = 0; i < 16; i += 4) {
            float4 kv = *(const float4*)(p + i);
            kt[(qo + i + 0) * CST + t] = kv.x;
            kt[(qo + i + 1) * CST + t] = kv.y;
            kt[(qo + i + 2) * CST + t] = kv.z;
            kt[(qo + i + 3) * CST + t] = kv.w;
        }
    }
    {
        const int m = tid >> 2;
        const int qo = (tid & 3) * 16;
        const float* p = gS + idx * 4096 + (size_t)m * 64 + qo;
        float* dp = Sp + m * CST + qo;
        #pragma unroll
        for (int i = 0; i < 4; i++)
            *(float4*)(dp + i * 4) = *(const float4*)(p + i * 4);
    }
    if (tid < 64) zp[tid] = gZ[idx * 64 + tid];
    __syncthreads();

    const int ig = (tid >> 4) * 4;
    const int jg = (tid & 15) * 4;

    float a[4][4];
    float qz[4];
    #pragma unroll
    for (int e = 0; e < 4; e++) {
        qz[e] = 0.f;
        #pragma unroll
        for (int c = 0; c < 4; c++) a[e][c] = 0.f;
    }
    #pragma unroll 4
    for (int m = 0; m < DH; m++) {
        const float zv = zp[m];
        float4 k4 = *(const float4*)(kt + m * CST + jg);
        #pragma unroll
        for (int e = 0; e < 4; e++) {
            const float qv = qs[(ig + e) * CST + m];
            qz[e] = fmaf(qv, zv, qz[e]);
            a[e][0] = fmaf(qv, k4.x, a[e][0]);
            a[e][1] = fmaf(qv, k4.y, a[e][1]);
            a[e][2] = fmaf(qv, k4.z, a[e][2]);
            a[e][3] = fmaf(qv, k4.w, a[e][3]);
        }
    }
    float den[4];
    #pragma unroll
    for (int e = 0; e < 4; e++) {
        const int i = ig + e;
        #pragma unroll
        for (int c = 0; c < 4; c++)
            if (jg + c > i) a[e][c] = 0.f;
        float rs = a[e][0] + a[e][1] + a[e][2] + a[e][3];
        rs += __shfl_xor_sync(0xffffffffu, rs, 1);
        rs += __shfl_xor_sync(0xffffffffu, rs, 2);
        rs += __shfl_xor_sync(0xffffffffu, rs, 4);
        rs += __shfl_xor_sync(0xffffffffu, rs, 8);
        den[e] = qz[e] + rs + 1e-6f;
        *(float4*)(Am + i * CST + jg) = make_float4(a[e][0], a[e][1], a[e][2], a[e][3]);
    }
    __syncthreads();

    float acc[4][4];
    #pragma unroll
    for (int e = 0; e < 4; e++)
        #pragma unroll
        for (int c = 0; c < 4; c++) acc[e][c] = 0.f;

    #pragma unroll 4
    for (int m = 0; m < DH; m++) {
        float4 s4 = *(const float4*)(Sp + m * CST + jg);
        #pragma unroll
        for (int e = 0; e < 4; e++) {
            const float qv = qs[(ig + e) * CST + m];
            acc[e][0] = fmaf(qv, s4.x, acc[e][0]);
            acc[e][1] = fmaf(qv, s4.y, acc[e][1]);
            acc[e][2] = fmaf(qv, s4.z, acc[e][2]);
            acc[e][3] = fmaf(qv, s4.w, acc[e][3]);
        }
    }
    const int jmax = ig + 3;
    for (int j = 0; j <= jmax; j++) {
        float4 v4 = *(const float4*)(vs + j * CST + jg);
        #pragma unroll
        for (int e = 0; e < 4; e++) {
            const float av = Am[(ig + e) * CST + j];
            acc[e][0] = fmaf(av, v4.x, acc[e][0]);
            acc[e][1] = fmaf(av, v4.y, acc[e][1]);
            acc[e][2] = fmaf(av, v4.z, acc[e][2]);
            acc[e][3] = fmaf(av, v4.w, acc[e][3]);
        }
    }

    #pragma unroll
    for (int e = 0; e < 4; e++) {
        const float inv = 1.f / den[e];
        float* op = Out + gbase + (size_t)(ig + e) * D_MODEL + jg;
        *(float4*)op = make_float4(roundtf(acc[e][0] * inv), roundtf(acc[e][1] * inv),
                                   roundtf(acc[e][2] * inv), roundtf(acc[e][3] * inv));
    }
}
#define ATTN_SMEM ((5 * 64 * CST + 64) * 4)

// ---------------- LayerNorm: out = LN(a + r) * g + b ; optional rounded copy ----------------
__global__ __launch_bounds__(256) void ln_kernel(
    float* __restrict__ out, const float* __restrict__ a,
    const float* __restrict__ r, const float* __restrict__ gam,
    const float* __restrict__ bet, float* __restrict__ outr)
{
    const int row = blockIdx.x;
    const int tid = threadIdx.x;
    const float* pa = a + (size_t)row * D_MODEL;
    const float* pr = r + (size_t)row * D_MODEL;

    float v[4];
    float s = 0.f, ss = 0.f;
    #pragma unroll
    for (int i = 0; i < 4; i++) {
        int idx = tid + i * 256;
        float t = pa[idx] + pr[idx];
        v[i] = t; s += t; ss = fmaf(t, t, ss);
    }

    __shared__ float red[18];
    #pragma unroll
    for (int o = 16; o; o >>= 1) {
        s  += __shfl_xor_sync(0xffffffffu, s,  o);
        ss += __shfl_xor_sync(0xffffffffu, ss, o);
    }
    const int w = tid >> 5, lane = tid & 31;
    __shared__ float rw[16];
    if (lane == 0) { rw[w] = s; rw[w + 8] = ss; }
    __syncthreads();
    if (tid == 0) {
        float S0 = 0.f, S1 = 0.f;
        #pragma unroll
        for (int i = 0; i < 8; i++) { S0 += rw[i]; S1 += rw[i + 8]; }
        red[16] = S0; red[17] = S1;
    }
    __syncthreads();

    const float mean = red[16] * (1.f / 1024.f);
    const float var  = red[17] * (1.f / 1024.f) - mean * mean;
    const float inv  = rsqrtf(var + 1e-5f);

    float* po = out + (size_t)row * D_MODEL;
    float* pq = (outr != nullptr) ? outr + (size_t)row * D_MODEL : nullptr;
    #pragma unroll
    for (int i = 0; i < 4; i++) {
        int idx = tid + i * 256;
        float o = (v[i] - mean) * inv * gam[idx] + bet[idx];
        po[idx] = o;
        if (pq) pq[idx] = roundtf(o);
    }
}

// ---------------- launch ----------------
extern "C" void kernel_launch(void* const* d_in, const int* in_sizes, int n_in,
                              void* d_out, int out_size)
{
    const float* x    = (const float*)d_in[0];
    const float* Wq   = (const float*)d_in[1];
    const float* bq   = (const float*)d_in[2];
    const float* Wk   = (const float*)d_in[3];
    const float* bk   = (const float*)d_in[4];
    const float* Wv   = (const float*)d_in[5];
    const float* bv   = (const float*)d_in[6];
    const float* Wo   = (const float*)d_in[7];
    const float* bo   = (const float*)d_in[8];
    const float* omg  = (const float*)d_in[9];
    const float* ln1g = (const float*)d_in[10];
    const float* ln1b = (const float*)d_in[11];
    const float* ln2g = (const float*)d_in[12];
    const float* ln2b = (const float*)d_in[13];
    const float* W1   = (const float*)d_in[14];
    const float* bf1  = (const float*)d_in[15];
    const float* W2   = (const float*)d_in[16];
    const float* bf2  = (const float*)d_in[17];
    float* out = (float*)d_out;

    float *cur, *q, *k, *v, *qf, *kf, *h, *hr, *xr, *ffn, *gS, *gZ;
    cudaGetSymbolAddress((void**)&cur, g_cur);
    cudaGetSymbolAddress((void**)&q,   g_q);
    cudaGetSymbolAddress((void**)&k,   g_k);
    cudaGetSymbolAddress((void**)&v,   g_v);
    cudaGetSymbolAddress((void**)&qf,  g_qf);
    cudaGetSymbolAddress((void**)&kf,  g_kf);
    cudaGetSymbolAddress((void**)&h,   g_h);
    cudaGetSymbolAddress((void**)&hr,  g_hr);
    cudaGetSymbolAddress((void**)&xr,  g_xr);
    cudaGetSymbolAddress((void**)&ffn, g_ffn);
    cudaGetSymbolAddress((void**)&gS,  g_S);
    cudaGetSymbolAddress((void**)&gZ,  g_Z);

    cudaFuncSetAttribute(mma_gemm, cudaFuncAttributeMaxDynamicSharedMemorySize, GEMM_SMEM);
    cudaFuncSetAttribute(chunk_attn_kernel, cudaFuncAttributeMaxDynamicSharedMemorySize, ATTN_SMEM);

    // -------- prep: tf32-round layer-0 activation only --------
    const int nX4 = NTOK * D_MODEL / 4;
    round_kernel<<<nX4 / 256, 256>>>(x, xr, nX4);

    const dim3 gQKV(D_MODEL / 128, NTOK / 128, 3);
    const dim3 gD(D_MODEL / 128, NTOK / 128, 1);
    const dim3 gF(DFF_DIM / 128, NTOK / 128, 1);
    const dim3 gCh(NCHUNK, 32);
    const dim3 gFav(NTOK * NHEAD / 8, 2);
    const int  gPref = (32 * 4096) / 256;

    for (int l = 0; l < NLAYER; l++) {
        const size_t wDD  = (size_t)l * D_MODEL * D_MODEL;
        const size_t wDF  = (size_t)l * D_MODEL * DFF_DIM;
        const size_t bD   = (size_t)l * D_MODEL;
        const size_t bF   = (size_t)l * DFF_DIM;
        const size_t oOff = (size_t)l * DH * 32;
        const float* resA = (l == 0) ? x : cur;   // raw residual input

        mma_gemm<<<gQKV, 512, GEMM_SMEM>>>(xr,
            Wq + wDD, Wk + wDD, Wv + wDD,
            bq + bD, bk + bD, bv + bD,
            q, k, v, NTOK, D_MODEL, D_MODEL, 0);

        favor_kernel<<<gFav, 256>>>(q, k, omg + oOff, qf, kf);

        chunk_sums_kernel<<<gCh, 256>>>(kf, v, gS, gZ);
        chunk_prefix_kernel<<<gPref, 256>>>(gS, gZ);
        chunk_attn_kernel<<<gCh, 256, ATTN_SMEM>>>(qf, kf, v, gS, gZ, q);  // attn -> q (rounded)

        mma_gemm<<<gD, 512, GEMM_SMEM>>>(q,
            Wo + wDD, Wo + wDD, Wo + wDD,
            bo + bD, bo + bD, bo + bD,
            k, k, k, NTOK, D_MODEL, D_MODEL, 0);
        ln_kernel<<<NTOK, 256>>>(h, resA, k, ln1g + bD, ln1b + bD, hr);

        mma_gemm<<<gF, 512, GEMM_SMEM>>>(hr,
            W1 + wDF, W1 + wDF, W1 + wDF,
            bf1 + bF, bf1 + bF, bf1 + bF,
            ffn, ffn, ffn, NTOK, DFF_DIM, D_MODEL, 1);
        mma_gemm<<<gD, 512, GEMM_SMEM>>>(ffn,
            W2 + wDF, W2 + wDF, W2 + wDF,
            bf2 + bD, bf2 + bD, bf2 + bD,
            v, v, v, NTOK, D_MODEL, DFF_DIM, 0);

        const bool last = (l == NLAYER - 1);
        float* dst = last ? out : cur;
        ln_kernel<<<NTOK, 256>>>(dst, h, v, ln2g + bD, ln2b + bD, last ? nullptr : xr);
    }
}

// round 13
// speedup vs baseline: 1.0287x; 1.0017x over previous
#include <cuda_runtime.h>
#include <cstdint>
#include <math.h>

// ---------------- problem constants ----------------
#define D_MODEL 1024
#define DFF_DIM 4096
#define NTOK    2048          // B*S = 2*1024
#define NHEAD   16
#define DH      64
#define NLAYER  3
#define NCHUNK  16            // chunks per sequence
#define CLEN    64            // tokens per chunk

// ---------------- scratch (no allocs allowed) ----------------
__device__ float g_cur[NTOK * D_MODEL];
__device__ float g_q  [NTOK * D_MODEL];
__device__ float g_k  [NTOK * D_MODEL];
__device__ float g_v  [NTOK * D_MODEL];
__device__ float g_h  [NTOK * D_MODEL];
__device__ float g_hr [NTOK * D_MODEL];      // tf32-rounded h (FFN1 A operand)
__device__ float g_xr [NTOK * D_MODEL];      // tf32-rounded activation (QKV A operand)
__device__ float g_ffn[NTOK * DFF_DIM];
__device__ float g_S  [32 * NCHUNK * DH * DH];
__device__ float g_Z  [32 * NCHUNK * DH];

// ================= helpers =================
__device__ __forceinline__ uint32_t f2tf32(float f) {
    uint32_t u;
    asm("cvt.rna.tf32.f32 %0, %1;" : "=r"(u) : "f"(f));
    return u;
}
__device__ __forceinline__ float roundtf(float f) {
    return __uint_as_float(f2tf32(f));
}
__device__ __forceinline__ uint32_t smem_u32(const void* p) {
    uint32_t a;
    asm("{ .reg .u64 t; cvta.to.shared.u64 t, %1; cvt.u32.u64 %0, t; }" : "=r"(a) : "l"(p));
    return a;
}
__device__ __forceinline__ void mma_tf32(float c[4], uint32_t a0, uint32_t a1,
                                         uint32_t a2, uint32_t a3,
                                         uint32_t b0, uint32_t b1) {
    asm volatile(
        "mma.sync.aligned.m16n8k8.row.col.f32.tf32.tf32.f32 "
        "{%0,%1,%2,%3}, {%4,%5,%6,%7}, {%8,%9}, {%0,%1,%2,%3};"
        : "+f"(c[0]), "+f"(c[1]), "+f"(c[2]), "+f"(c[3])
        : "r"(a0), "r"(a1), "r"(a2), "r"(a3), "r"(b0), "r"(b1));
}
#define CP16(dst, src) \
    asm volatile("cp.async.cg.shared.global [%0], [%1], 16;" :: "r"(dst), "l"(src) : "memory")
#define CP_COMMIT() asm volatile("cp.async.commit_group;" ::: "memory")
#define CP_WAIT0()  asm volatile("cp.async.wait_group 0;" ::: "memory")

// ---------------- tf32 rounding copy (layer-0 x only) ----------------
__global__ void round_kernel(const float* __restrict__ src, float* __restrict__ dst, int n4)
{
    int i = blockIdx.x * blockDim.x + threadIdx.x;
    if (i < n4) {
        float4 v = ((const float4*)src)[i];
        uint4 u;
        u.x = f2tf32(v.x); u.y = f2tf32(v.y);
        u.z = f2tf32(v.z); u.w = f2tf32(v.w);
        ((uint4*)dst)[i] = u;
    }
}

// ================= TF32 tensor-core GEMM — hybrid staging (proven, unchanged) =================
#define BK      64
#define ASTRIDE 68
#define BSTRIDE 168
#define ABUF (128 * ASTRIDE)
#define BBUF (64 * BSTRIDE)
#define GEMM_SMEM ((2 * ABUF + 2 * BBUF) * 4)

__global__ __launch_bounds__(512, 1) void mma_gemm(
    const float* __restrict__ A,
    const float* __restrict__ B0, const float* __restrict__ B1, const float* __restrict__ B2,
    const float* __restrict__ bias0, const float* __restrict__ bias1, const float* __restrict__ bias2,
    float* __restrict__ C0, float* __restrict__ C1, float* __restrict__ C2,
    int M, int N, int K, int do_relu)
{
    extern __shared__ float sm[];
    const uint32_t smb = smem_u32(sm);

    const int z = blockIdx.z;
    const float* B    = (z == 0) ? B0 : (z == 1) ? B1 : B2;
    const float* bias = (z == 0) ? bias0 : (z == 1) ? bias1 : bias2;
    float* C          = (z == 0) ? C0 : (z == 1) ? C1 : C2;

    const int tid  = threadIdx.x;
    const int bm   = blockIdx.y * 128;
    const int bn   = blockIdx.x * 128;
    const int lane = tid & 31;
    const int warp = tid >> 5;          // 0..15
    const int g    = lane >> 2;
    const int t    = lane & 3;
    const int m0   = (warp & 3) * 32;
    const int n0   = (warp >> 2) * 32;

    float acc[2][4][4];
    #pragma unroll
    for (int i = 0; i < 2; i++)
        #pragma unroll
        for (int j = 0; j < 4; j++)
            #pragma unroll
            for (int e = 0; e < 4; e++) acc[i][j][e] = 0.f;

    const int ar = tid >> 2;              // 0..127
    const int ac = (tid & 3) * 8;         // 0,8,16,24
    const int br = tid >> 4;              // 0..31
    const int bc = (tid & 15) * 8;        // 0..120
    const int bcp = bc + ((bc >> 5) << 2);

    const float* Abase = A + (size_t)(bm + ar) * K + ac;
    const float* Bbase = B + (size_t)br * N + bn + bc;
    const uint32_t aoff = 4u * (uint32_t)(ar * ASTRIDE + ac);

    int cnp[4];
    #pragma unroll
    for (int nf = 0; nf < 4; nf++) {
        const int cb = n0 + nf * 8;
        cnp[nf] = cb + ((cb >> 5) << 2) + g;
    }

    const int NC = K / BK;

    auto issueA = [&](int buf, int k0) {
        #pragma unroll
        for (int half = 0; half < 2; half++) {
            const int koff = half * 32;
            const float* asrc = Abase + k0 + koff;
            uint32_t adst = smb + 4u * (uint32_t)(buf * ABUF) + aoff + 4u * (uint32_t)koff;
            CP16(adst, asrc);
            CP16(adst + 16u, asrc + 4);
        }
    };
    auto ldgB = [&](int k0, int koff, float4 pb[2]) {
        const float* bsrc = Bbase + (size_t)(k0 + koff) * N;
        pb[0] = *(const float4*)(bsrc);
        pb[1] = *(const float4*)(bsrc + 4);
    };
    auto stsB = [&](float* Bd, int koff, const float4 pb[2]) {
        #pragma unroll
        for (int i = 0; i < 2; i++) {
            uint4 u;
            u.x = f2tf32(pb[i].x); u.y = f2tf32(pb[i].y);
            u.z = f2tf32(pb[i].z); u.w = f2tf32(pb[i].w);
            *(uint4*)(Bd + (koff + br) * BSTRIDE + bcp + i * 4) = u;
        }
    };

    issueA(0, 0);
    CP_COMMIT();
    {
        float4 pb[2];
        ldgB(0, 0, pb);  stsB(sm + 2 * ABUF, 0, pb);
        ldgB(0, 32, pb); stsB(sm + 2 * ABUF, 32, pb);
    }
    CP_WAIT0();
    __syncthreads();

    for (int c = 0; c < NC; c++) {
        const int buf = c & 1;
        const int nb  = buf ^ 1;
        const bool more = (c + 1 < NC);
        float* Bd = sm + 2 * ABUF + nb * BBUF;
        float4 pb[2];

        if (more) {
            issueA(nb, (c + 1) * BK);
            CP_COMMIT();
            ldgB((c + 1) * BK, 0, pb);
        }

        const uint32_t* Au = (const uint32_t*)(sm + buf * ABUF);
        const uint32_t* Bu = (const uint32_t*)(sm + 2 * ABUF + buf * BBUF);

        #pragma unroll
        for (int ks = 0; ks < 4; ks++) {
            const int kk = ks * 8;
            uint32_t af[2][4];
            #pragma unroll
            for (int mf = 0; mf < 2; mf++) {
                const int r = m0 + mf * 16 + g;
                af[mf][0] = Au[r * ASTRIDE + kk + t];
                af[mf][1] = Au[(r + 8) * ASTRIDE + kk + t];
                af[mf][2] = Au[r * ASTRIDE + kk + t + 4];
                af[mf][3] = Au[(r + 8) * ASTRIDE + kk + t + 4];
            }
            #pragma unroll
            for (int nf = 0; nf < 4; nf++) {
                uint32_t b0 = Bu[(kk + t) * BSTRIDE + cnp[nf]];
                uint32_t b1 = Bu[(kk + t + 4) * BSTRIDE + cnp[nf]];
                #pragma unroll
                for (int mf = 0; mf < 2; mf++)
                    mma_tf32(acc[mf][nf], af[mf][0], af[mf][1], af[mf][2], af[mf][3], b0, b1);
            }
        }

        if (more) {
            stsB(Bd, 0, pb);
            ldgB((c + 1) * BK, 32, pb);
        }

        #pragma unroll
        for (int ks = 4; ks < 8; ks++) {
            const int kk = ks * 8;
            uint32_t af[2][4];
            #pragma unroll
            for (int mf = 0; mf < 2; mf++) {
                const int r = m0 + mf * 16 + g;
                af[mf][0] = Au[r * ASTRIDE + kk + t];
                af[mf][1] = Au[(r + 8) * ASTRIDE + kk + t];
                af[mf][2] = Au[r * ASTRIDE + kk + t + 4];
                af[mf][3] = Au[(r + 8) * ASTRIDE + kk + t + 4];
            }
            #pragma unroll
            for (int nf = 0; nf < 4; nf++) {
                uint32_t b0 = Bu[(kk + t) * BSTRIDE + cnp[nf]];
                uint32_t b1 = Bu[(kk + t + 4) * BSTRIDE + cnp[nf]];
                #pragma unroll
                for (int mf = 0; mf < 2; mf++)
                    mma_tf32(acc[mf][nf], af[mf][0], af[mf][1], af[mf][2], af[mf][3], b0, b1);
            }
        }

        if (more) {
            stsB(Bd, 32, pb);
            CP_WAIT0();
            __syncthreads();
        }
    }

    #pragma unroll
    for (int mf = 0; mf < 2; mf++) {
        const int r0 = bm + m0 + mf * 16 + g;
        #pragma unroll
        for (int nf = 0; nf < 4; nf++) {
            const int col = bn + n0 + nf * 8 + 2 * t;
            const float b0 = bias[col], b1 = bias[col + 1];
            float2 o0, o1;
            o0.x = acc[mf][nf][0] + b0; o0.y = acc[mf][nf][1] + b1;
            o1.x = acc[mf][nf][2] + b0; o1.y = acc[mf][nf][3] + b1;
            if (do_relu) {
                o0.x = roundtf(fmaxf(o0.x, 0.f)); o0.y = roundtf(fmaxf(o0.y, 0.f));
                o1.x = roundtf(fmaxf(o1.x, 0.f)); o1.y = roundtf(fmaxf(o1.y, 0.f));
            }
            *(float2*)(C + (size_t)r0 * N + col)       = o0;
            *(float2*)(C + (size_t)(r0 + 8) * N + col) = o1;
        }
    }
}

// ============ chunked causal linear attention with fused FAVOR ============
#define CST 68   // smem tile stride (words)
#define OMS 33   // omega smem stride

__device__ __forceinline__ void load_tile(
    float* dst, const float* __restrict__ src, size_t gbase, int tid)
{
    const int t = tid >> 2;
    const int qo = (tid & 3) * 16;
    const float* p = src + gbase + (size_t)t * D_MODEL + qo;
    float* d = dst + t * CST + qo;
    #pragma unroll
    for (int i = 0; i < 4; i++)
        *(float4*)(d + i * 4) = *(const float4*)(p + i * 4);
}

// compute u[8] (this thread's 8 of 32 projections) and h for one token row
__device__ __forceinline__ void favor_uh(
    const float* __restrict__ row, const float* __restrict__ om,
    int grp, float u[8], float& h)
{
    const float scale = 0.35355339059327373f;   // 64^-0.25
    #pragma unroll
    for (int jj = 0; jj < 8; jj++) u[jj] = 0.f;
    h = 0.f;
    #pragma unroll 4
    for (int d = 0; d < DH; d++) {
        const float xs = row[d] * scale;
        h = fmaf(xs, xs, h);
        const float* omd = om + d * OMS + grp * 8;
        #pragma unroll
        for (int jj = 0; jj < 8; jj++)
            u[jj] = fmaf(xs, omd[jj], u[jj]);
    }
    h *= 0.5f;
}

// Phase 1: S_c[m][d] = sum_t kf[t][m] v[t][d] ; z_c[m] = sum_t kf[t][m]
// kf computed in-kernel from raw K and omega.
#define SUMS_SMEM ((3 * 64 * CST + 64 * OMS) * 4)
__global__ __launch_bounds__(256) void chunk_sums_kernel(
    const float* __restrict__ Kraw, const float* __restrict__ V,
    const float* __restrict__ omega,
    float* __restrict__ gS, float* __restrict__ gZ)
{
    extern __shared__ float s1[];
    float* kr = s1;                    // raw k tile [tok][d]
    float* vs = s1 + 64 * CST;
    float* kf = s1 + 2 * 64 * CST;     // feature tile [tok][m]
    float* om = s1 + 3 * 64 * CST;     // [d][j] stride OMS

    const int ch = blockIdx.x;
    const int bh = blockIdx.y;
    const int tid = threadIdx.x;
    const int b = bh >> 4, hd = bh & 15;
    const size_t gbase = (size_t)b * 1024 * D_MODEL + (size_t)(ch * CLEN) * D_MODEL + hd * DH;

    load_tile(kr, Kraw, gbase, tid);
    load_tile(vs, V,  gbase, tid);
    for (int i = tid; i < DH * 32; i += 256)
        om[(i >> 5) * OMS + (i & 31)] = omega[i];
    __syncthreads();

    // FAVOR on k tile
    {
        const int tok = tid >> 2, grp = tid & 3;
        float u[8], h;
        favor_uh(kr + tok * CST, om, grp, u, h);
        float* kfr = kf + tok * CST + grp * 8;
        #pragma unroll
        for (int jj = 0; jj < 8; jj++) {
            kfr[jj]      = expf(u[jj]  - h) * 0.125f;
            kfr[32 + jj] = expf(-u[jj] - h) * 0.125f;
        }
    }
    __syncthreads();

    const int mg = (tid >> 4) * 4;
    const int dg = (tid & 15) * 4;

    float acc[4][4];
    float zz[4];
    #pragma unroll
    for (int e = 0; e < 4; e++) {
        zz[e] = 0.f;
        #pragma unroll
        for (int c = 0; c < 4; c++) acc[e][c] = 0.f;
    }

    #pragma unroll 4
    for (int t = 0; t < CLEN; t++) {
        float4 v4 = *(const float4*)(vs + t * CST + dg);
        #pragma unroll
        for (int e = 0; e < 4; e++) {
            const float kv = kf[t * CST + mg + e];
            zz[e] += kv;
            acc[e][0] = fmaf(kv, v4.x, acc[e][0]);
            acc[e][1] = fmaf(kv, v4.y, acc[e][1]);
            acc[e][2] = fmaf(kv, v4.z, acc[e][2]);
            acc[e][3] = fmaf(kv, v4.w, acc[e][3]);
        }
    }

    const size_t idx = (size_t)(bh * NCHUNK + ch);
    #pragma unroll
    for (int e = 0; e < 4; e++)
        *(float4*)(gS + idx * 4096 + (size_t)(mg + e) * 64 + dg) =
            make_float4(acc[e][0], acc[e][1], acc[e][2], acc[e][3]);
    if ((tid & 15) == 0) {
        #pragma unroll
        for (int e = 0; e < 4; e++) gZ[idx * 64 + mg + e] = zz[e];
    }
}

// Phase 2: exclusive prefix over 16 chunks — one thread per (bh, element).
__global__ __launch_bounds__(256) void chunk_prefix_kernel(
    float* __restrict__ gS, float* __restrict__ gZ)
{
    const int gid = blockIdx.x * 256 + threadIdx.x;   // 0 .. 131071
    const int bh = gid >> 12;
    const int e  = gid & 4095;

    const size_t base = (size_t)bh * (NCHUNK * 4096) + e;
    float vals[NCHUNK];
    #pragma unroll
    for (int ch = 0; ch < NCHUNK; ch++)
        vals[ch] = gS[base + (size_t)ch * 4096];

    float run = 0.f;
    #pragma unroll
    for (int ch = 0; ch < NCHUNK; ch++) {
        const float t = vals[ch];
        gS[base + (size_t)ch * 4096] = run;
        run += t;
    }

    if (e < 64) {
        const size_t zbase = (size_t)bh * (NCHUNK * 64) + e;
        float zv[NCHUNK];
        #pragma unroll
        for (int ch = 0; ch < NCHUNK; ch++)
            zv[ch] = gZ[zbase + ch * 64];
        float zr = 0.f;
        #pragma unroll
        for (int ch = 0; ch < NCHUNK; ch++) {
            const float t = zv[ch];
            gZ[zbase + ch * 64] = zr;
            zr += t;
        }
    }
}

// Phase 3: token-parallel intra-chunk attention with fused FAVOR.
// qf computed in-place over the raw q tile; kf^T via the Am buffer as scratch.
#define ATTN_SMEM ((5 * 64 * CST + 64 + 64 * OMS) * 4)
__global__ __launch_bounds__(256) void chunk_attn_kernel(
    const float* __restrict__ Qraw, const float* __restrict__ Kraw,
    const float* __restrict__ V, const float* __restrict__ omega,
    const float* __restrict__ gS, const float* __restrict__ gZ,
    float* __restrict__ Out)
{
    extern __shared__ float smw[];
    float* qs = smw;                 // raw q -> qf, [i][m]
    float* kt = smw + 64 * CST;      // kf^T [m][j]
    float* vs = smw + 2 * 64 * CST;  // [j][d]
    float* Sp = smw + 3 * 64 * CST;  // [m][d]
    float* Am = smw + 4 * 64 * CST;  // scratch: raw k, then masked A [i][j]
    float* zp = smw + 5 * 64 * CST;  // [m]
    float* om = smw + 5 * 64 * CST + 64;

    const int ch = blockIdx.x;
    const int bh = blockIdx.y;
    const int tid = threadIdx.x;
    const int b = bh >> 4, hd = bh & 15;
    const size_t gbase = (size_t)b * 1024 * D_MODEL + (size_t)(ch * CLEN) * D_MODEL + hd * DH;
    const size_t idx = (size_t)(bh * NCHUNK + ch);

    load_tile(qs, Qraw, gbase, tid);   // raw q
    load_tile(Am, Kraw, gbase, tid);   // raw k (scratch)
    load_tile(vs, V,  gbase, tid);
    {
        const int m = tid >> 2;
        const int qo = (tid & 3) * 16;
        const float* p = gS + idx * 4096 + (size_t)m * 64 + qo;
        float* dp = Sp + m * CST + qo;
        #pragma unroll
        for (int i = 0; i < 4; i++)
            *(float4*)(dp + i * 4) = *(const float4*)(p + i * 4);
    }
    if (tid < 64) zp[tid] = gZ[idx * 64 + tid];
    for (int i = tid; i < DH * 32; i += 256)
        om[(i >> 5) * OMS + (i & 31)] = omega[i];
    __syncthreads();

    // FAVOR: compute u/h for q (from qs) and k (from Am) into registers
    const int tok = tid >> 2, grp = tid & 3;
    float uq[8], hq, uk[8], hk;
    favor_uh(qs + tok * CST, om, grp, uq, hq);
    favor_uh(Am + tok * CST, om, grp, uk, hk);
    __syncthreads();   // all raw reads done before overwrite

    {
        float* qfr = qs + tok * CST + grp * 8;
        #pragma unroll
        for (int jj = 0; jj < 8; jj++) {
            qfr[jj]      = expf(uq[jj]  - hq) * 0.125f;
            qfr[32 + jj] = expf(-uq[jj] - hq) * 0.125f;
        }
        const int jb = grp * 8;
        #pragma unroll
        for (int jj = 0; jj < 8; jj++) {
            kt[(jb + jj) * CST + tok]      = expf(uk[jj]  - hk) * 0.125f;
            kt[(32 + jb + jj) * CST + tok] = expf(-uk[jj] - hk) * 0.125f;
        }
    }
    __syncthreads();

    const int ig = (tid >> 4) * 4;
    const int jg = (tid & 15) * 4;

    float a[4][4];
    float qz[4];
    #pragma unroll
    for (int e = 0; e < 4; e++) {
        qz[e] = 0.f;
        #pragma unroll
        for (int c = 0; c < 4; c++) a[e][c] = 0.f;
    }
    #pragma unroll 4
    for (int m = 0; m < DH; m++) {
        const float zv = zp[m];
        float4 k4 = *(const float4*)(kt + m * CST + jg);
        #pragma unroll
        for (int e = 0; e < 4; e++) {
            const float qv = qs[(ig + e) * CST + m];
            qz[e] = fmaf(qv, zv, qz[e]);
            a[e][0] = fmaf(qv, k4.x, a[e][0]);
            a[e][1] = fmaf(qv, k4.y, a[e][1]);
            a[e][2] = fmaf(qv, k4.z, a[e][2]);
            a[e][3] = fmaf(qv, k4.w, a[e][3]);
        }
    }
    float den[4];
    #pragma unroll
    for (int e = 0; e < 4; e++) {
        const int i = ig + e;
        #pragma unroll
        for (int c = 0; c < 4; c++)
            if (jg + c > i) a[e][c] = 0.f;
        float rs = a[e][0] + a[e][1] + a[e][2] + a[e][3];
        rs += __shfl_xor_sync(0xffffffffu, rs, 1);
        rs += __shfl_xor_sync(0xffffffffu, rs, 2);
        rs += __shfl_xor_sync(0xffffffffu, rs, 4);
        rs += __shfl_xor_sync(0xffffffffu, rs, 8);
        den[e] = qz[e] + rs + 1e-6f;
        *(float4*)(Am + i * CST + jg) = make_float4(a[e][0], a[e][1], a[e][2], a[e][3]);
    }
    __syncthreads();

    float acc[4][4];
    #pragma unroll
    for (int e = 0; e < 4; e++)
        #pragma unroll
        for (int c = 0; c < 4; c++) acc[e][c] = 0.f;

    #pragma unroll 4
    for (int m = 0; m < DH; m++) {
        float4 s4 = *(const float4*)(Sp + m * CST + jg);
        #pragma unroll
        for (int e = 0; e < 4; e++) {
            const float qv = qs[(ig + e) * CST + m];
            acc[e][0] = fmaf(qv, s4.x, acc[e][0]);
            acc[e][1] = fmaf(qv, s4.y, acc[e][1]);
            acc[e][2] = fmaf(qv, s4.z, acc[e][2]);
            acc[e][3] = fmaf(qv, s4.w, acc[e][3]);
        }
    }
    const int jmax = ig + 3;
    for (int j = 0; j <= jmax; j++) {
        float4 v4 = *(const float4*)(vs + j * CST + jg);
        #pragma unroll
        for (int e = 0; e < 4; e++) {
            const float av = Am[(ig + e) * CST + j];
            acc[e][0] = fmaf(av, v4.x, acc[e][0]);
            acc[e][1] = fmaf(av, v4.y, acc[e][1]);
            acc[e][2] = fmaf(av, v4.z, acc[e][2]);
            acc[e][3] = fmaf(av, v4.w, acc[e][3]);
        }
    }

    #pragma unroll
    for (int e = 0; e < 4; e++) {
        const float inv = 1.f / den[e];
        float* op = Out + gbase + (size_t)(ig + e) * D_MODEL + jg;
        *(float4*)op = make_float4(roundtf(acc[e][0] * inv), roundtf(acc[e][1] * inv),
                                   roundtf(acc[e][2] * inv), roundtf(acc[e][3] * inv));
    }
}

// ---------------- LayerNorm: out = LN(a + r) * g + b ; optional rounded copy ----------------
__global__ __launch_bounds__(256) void ln_kernel(
    float* __restrict__ out, const float* __restrict__ a,
    const float* __restrict__ r, const float* __restrict__ gam,
    const float* __restrict__ bet, float* __restrict__ outr)
{
    const int row = blockIdx.x;
    const int tid = threadIdx.x;
    const float* pa = a + (size_t)row * D_MODEL;
    const float* pr = r + (size_t)row * D_MODEL;

    float v[4];
    float s = 0.f, ss = 0.f;
    #pragma unroll
    for (int i = 0; i < 4; i++) {
        int idx = tid + i * 256;
        float t = pa[idx] + pr[idx];
        v[i] = t; s += t; ss = fmaf(t, t, ss);
    }

    __shared__ float red[18];
    #pragma unroll
    for (int o = 16; o; o >>= 1) {
        s  += __shfl_xor_sync(0xffffffffu, s,  o);
        ss += __shfl_xor_sync(0xffffffffu, ss, o);
    }
    const int w = tid >> 5, lane = tid & 31;
    __shared__ float rw[16];
    if (lane == 0) { rw[w] = s; rw[w + 8] = ss; }
    __syncthreads();
    if (tid == 0) {
        float S0 = 0.f, S1 = 0.f;
        #pragma unroll
        for (int i = 0; i < 8; i++) { S0 += rw[i]; S1 += rw[i + 8]; }
        red[16] = S0; red[17] = S1;
    }
    __syncthreads();

    const float mean = red[16] * (1.f / 1024.f);
    const float var  = red[17] * (1.f / 1024.f) - mean * mean;
    const float inv  = rsqrtf(var + 1e-5f);

    float* po = out + (size_t)row * D_MODEL;
    float* pq = (outr != nullptr) ? outr + (size_t)row * D_MODEL : nullptr;
    #pragma unroll
    for (int i = 0; i < 4; i++) {
        int idx = tid + i * 256;
        float o = (v[i] - mean) * inv * gam[idx] + bet[idx];
        po[idx] = o;
        if (pq) pq[idx] = roundtf(o);
    }
}

// ---------------- launch ----------------
extern "C" void kernel_launch(void* const* d_in, const int* in_sizes, int n_in,
                              void* d_out, int out_size)
{
    const float* x    = (const float*)d_in[0];
    const float* Wq   = (const float*)d_in[1];
    const float* bq   = (const float*)d_in[2];
    const float* Wk   = (const float*)d_in[3];
    const float* bk   = (const float*)d_in[4];
    const float* Wv   = (const float*)d_in[5];
    const float* bv   = (const float*)d_in[6];
    const float* Wo   = (const float*)d_in[7];
    const float* bo   = (const float*)d_in[8];
    const float* omg  = (const float*)d_in[9];
    const float* ln1g = (const float*)d_in[10];
    const float* ln1b = (const float*)d_in[11];
    const float* ln2g = (const float*)d_in[12];
    const float* ln2b = (const float*)d_in[13];
    const float* W1   = (const float*)d_in[14];
    const float* bf1  = (const float*)d_in[15];
    const float* W2   = (const float*)d_in[16];
    const float* bf2  = (const float*)d_in[17];
    float* out = (float*)d_out;

    float *cur, *q, *k, *v, *h, *hr, *xr, *ffn, *gS, *gZ;
    cudaGetSymbolAddress((void**)&cur, g_cur);
    cudaGetSymbolAddress((void**)&q,   g_q);
    cudaGetSymbolAddress((void**)&k,   g_k);
    cudaGetSymbolAddress((void**)&v,   g_v);
    cudaGetSymbolAddress((void**)&h,   g_h);
    cudaGetSymbolAddress((void**)&hr,  g_hr);
    cudaGetSymbolAddress((void**)&xr,  g_xr);
    cudaGetSymbolAddress((void**)&ffn, g_ffn);
    cudaGetSymbolAddress((void**)&gS,  g_S);
    cudaGetSymbolAddress((void**)&gZ,  g_Z);

    cudaFuncSetAttribute(mma_gemm, cudaFuncAttributeMaxDynamicSharedMemorySize, GEMM_SMEM);
    cudaFuncSetAttribute(chunk_sums_kernel, cudaFuncAttributeMaxDynamicSharedMemorySize, SUMS_SMEM);
    cudaFuncSetAttribute(chunk_attn_kernel, cudaFuncAttributeMaxDynamicSharedMemorySize, ATTN_SMEM);

    // prep: tf32-round layer-0 activation
    const int nX4 = NTOK * D_MODEL / 4;
    round_kernel<<<nX4 / 256, 256>>>(x, xr, nX4);

    const dim3 gQKV(D_MODEL / 128, NTOK / 128, 3);
    const dim3 gD(D_MODEL / 128, NTOK / 128, 1);
    const dim3 gF(DFF_DIM / 128, NTOK / 128, 1);
    const dim3 gCh(NCHUNK, 32);
    const int  gPref = (32 * 4096) / 256;

    for (int l = 0; l < NLAYER; l++) {
        const size_t wDD  = (size_t)l * D_MODEL * D_MODEL;
        const size_t wDF  = (size_t)l * D_MODEL * DFF_DIM;
        const size_t bD   = (size_t)l * D_MODEL;
        const size_t bF   = (size_t)l * DFF_DIM;
        const size_t oOff = (size_t)l * DH * 32;
        const float* resA = (l == 0) ? x : cur;

        mma_gemm<<<gQKV, 512, GEMM_SMEM>>>(xr,
            Wq + wDD, Wk + wDD, Wv + wDD,
            bq + bD, bk + bD, bv + bD,
            q, k, v, NTOK, D_MODEL, D_MODEL, 0);

        chunk_sums_kernel<<<gCh, 256, SUMS_SMEM>>>(k, v, omg + oOff, gS, gZ);
        chunk_prefix_kernel<<<gPref, 256>>>(gS, gZ);
        chunk_attn_kernel<<<gCh, 256, ATTN_SMEM>>>(q, k, v, omg + oOff, gS, gZ, q);

        mma_gemm<<<gD, 512, GEMM_SMEM>>>(q,
            Wo + wDD, Wo + wDD, Wo + wDD,
            bo + bD, bo + bD, bo + bD,
            k, k, k, NTOK, D_MODEL, D_MODEL, 0);
        ln_kernel<<<NTOK, 256>>>(h, resA, k, ln1g + bD, ln1b + bD, hr);

        mma_gemm<<<gF, 512, GEMM_SMEM>>>(hr,
            W1 + wDF, W1 + wDF, W1 + wDF,
            bf1 + bF, bf1 + bF, bf1 + bF,
            ffn, ffn, ffn, NTOK, DFF_DIM, D_MODEL, 1);
        mma_gemm<<<gD, 512, GEMM_SMEM>>>(ffn,
            W2 + wDF, W2 + wDF, W2 + wDF,
            bf2 + bD, bf2 + bD, bf2 + bD,
            v, v, v, NTOK, D_MODEL, DFF_DIM, 0);

        const bool last = (l == NLAYER - 1);
        float* dst = last ? out : cur;
        ln_kernel<<<NTOK, 256>>>(dst, h, v, ln2g + bD, ln2b + bD, last ? nullptr : xr);
    }
}